// round 16
// baseline (speedup 1.0000x reference)
#include <cuda_runtime.h>
#include <cuda_bf16.h>
#include <cstdint>

// Problem constants
#define BATCH   512
#define CIN     128
#define LIN     1024
#define KW      5
#define LOUT    1020
#define TSEQ    1020
#define H1      32
#define H2      16
#define H3      32
#define MROWS   (BATCH * TSEQ)   // 522240
#define NWALL   (TSEQ / 2 + 3)   // 513

// ---------------- scratch ----------------
__device__ uint32_t g_convb[(size_t)BATCH * 64 * LOUT];    // bf16-pair conv out
__device__ float    g_xg1 [(size_t)MROWS * 4 * H1];
__device__ uint32_t g_wtb  [5 * 128 * 64];                 // bf16-pair conv W: [tap][co][ci/2]
__device__ uint32_t g_w1b  [128 * 64];                     // bf16-pair Wih1: [row][k/2]

// ---------------- helpers ----------------
__device__ __forceinline__ float tanh_fast(float x) {
    float r; asm("tanh.approx.f32 %0, %1;" : "=f"(r) : "f"(x));
    return r;
}
__device__ __forceinline__ float sigmoid_fast(float x) {
    float r; asm("tanh.approx.f32 %0, %1;" : "=f"(r) : "f"(x * 0.5f));
    return fmaf(r, 0.5f, 0.5f);
}
__device__ __forceinline__ uint32_t pack_bf16(float lo, float hi) {
    uint32_t r;
    asm("cvt.rn.bf16x2.f32 %0, %1, %2;" : "=r"(r) : "f"(hi), "f"(lo));
    return r;
}
__device__ __forceinline__ void mma_bf16(float c[4], const uint32_t a[4], uint32_t b0, uint32_t b1) {
    asm volatile(
        "mma.sync.aligned.m16n8k16.row.col.f32.bf16.bf16.f32 "
        "{%0,%1,%2,%3}, {%4,%5,%6,%7}, {%8,%9}, {%0,%1,%2,%3};"
        : "+f"(c[0]), "+f"(c[1]), "+f"(c[2]), "+f"(c[3])
        : "r"(a[0]), "r"(a[1]), "r"(a[2]), "r"(a[3]), "r"(b0), "r"(b1));
}
__device__ __forceinline__ float2 ffma2(float2 a, float2 b, float2 c) {
    unsigned long long ua, ub, uc, ur;
    ua = *reinterpret_cast<unsigned long long*>(&a);
    ub = *reinterpret_cast<unsigned long long*>(&b);
    uc = *reinterpret_cast<unsigned long long*>(&c);
    asm("fma.rn.f32x2 %0, %1, %2, %3;" : "=l"(ur) : "l"(ua), "l"(ub), "l"(uc));
    return *reinterpret_cast<float2*>(&ur);
}
__device__ __forceinline__ uint32_t smem_u32(const void* p) {
    uint32_t a;
    asm("{ .reg .u64 t; cvta.to.shared.u64 t, %1; cvt.u32.u64 %0, t; }" : "=r"(a) : "l"(p));
    return a;
}
__device__ __forceinline__ void cp16(uint32_t dst, const void* src) {
    asm volatile("cp.async.ca.shared.global [%0], [%1], 16;" :: "r"(dst), "l"(src));
}
__device__ __forceinline__ void cp16n(uint32_t dst, const void* src, int nbytes) {
    asm volatile("cp.async.ca.shared.global [%0], [%1], 16, %2;" :: "r"(dst), "l"(src), "r"(nbytes));
}
#define CTA_BAR() asm volatile("bar.sync 0;" ::: "memory")

// H=32 LSTM cell step; i/f weights in regs, g/o weights from smem
__device__ __forceinline__ float lstm32_step_sm(
    const float2* __restrict__ hp,
    const float2* __restrict__ wif,
    const float2* __restrict__ swgo,
    float2 aif, float2 ago, float& cst)
{
    float2 aifB = make_float2(0.f, 0.f), agoB = make_float2(0.f, 0.f);
#pragma unroll
    for (int k = 0; k < 16; k++) {
        float2 hv = hp[k];
        aif = ffma2(hv, wif[k], aif);
        ago = ffma2(hv, swgo[k * 32], ago);
    }
#pragma unroll
    for (int k = 16; k < 32; k++) {
        float2 hv = hp[k];
        aifB = ffma2(hv, wif[k], aifB);
        agoB = ffma2(hv, swgo[k * 32], agoB);
    }
    float ig = sigmoid_fast(aif.x + aifB.x);
    float fg = sigmoid_fast(aif.y + aifB.y);
    float gg = tanh_fast(ago.x + agoB.x);
    float og = sigmoid_fast(ago.y + agoB.y);
    cst = fg * cst + ig * gg;
    return og * tanh_fast(cst);
}

// =====================================================================
// Prepack kernels (weights only; X handled inline by conv now)
// =====================================================================
__global__ void prep_wb_kernel(const float* __restrict__ w) {
    int i = blockIdx.x * 256 + threadIdx.x;
    if (i < 5 * 128 * 64) {
        int kp = i & 63;
        int r  = i >> 6;
        int co  = r & 127;
        int tap = r >> 7;
        float lo = w[((size_t)co * 128 + 2 * kp)     * 5 + tap];
        float hi = w[((size_t)co * 128 + 2 * kp + 1) * 5 + tap];
        g_wtb[i] = pack_bf16(lo, hi);
    }
}
__global__ void prep_w1_kernel(const float* __restrict__ W) {
    int i = blockIdx.x * 256 + threadIdx.x;
    if (i < 128 * 64) {
        int kp = i & 63;
        int r  = i >> 6;
        float2 wv = *reinterpret_cast<const float2*>(W + (size_t)r * 128 + 2 * kp);
        g_w1b[i] = pack_bf16(wv.x, wv.y);
    }
}

// =====================================================================
// conv1d via bf16 m16n8k16 MMA, 3-stage cp.async pipeline,
// X loaded as RAW fp32 and packed to bf16x2 at fragment-build time.
// 64co x 256l tile, grid (4, 512, 2), block 256.
// X smem stride 268 (bank-conflict-free fragment rows; 268*4 % 16 == 0)
// =====================================================================
#define CV5_WS_ST   (320 * 12)       // 3840 u32 per W stage
#define CV5_XS_ST   (16 * 268)       // 4288 f32 per X stage
#define CV5_XS_BASE (3 * CV5_WS_ST)  // 11520
#define CV5_SMEM_BYTES ((3 * CV5_WS_ST + 3 * CV5_XS_ST) * 4)   // 97536

__global__ __launch_bounds__(256, 2) void conv5_kernel(
    const float* __restrict__ x, const float* __restrict__ bias)
{
    extern __shared__ uint32_t smu[];
    const uint32_t sbase = smem_u32(smu);
    const uint32_t* Su = smu;

    const int b   = blockIdx.y;
    const int lb  = blockIdx.x * 256;
    const int co0 = blockIdx.z * 64;
    const int tid = threadIdx.x;
    const int warp = tid >> 5;
    const int lane = tid & 31;
    const int g   = lane >> 2;
    const int t4  = lane & 3;
    const int warp_m = warp >> 2;
    const int warp_n = warp & 3;

    float acc[2][8][4];
#pragma unroll
    for (int mi = 0; mi < 2; mi++)
#pragma unroll
        for (int ni = 0; ni < 8; ni++)
#pragma unroll
            for (int e = 0; e < 4; e++) acc[mi][ni][e] = 0.f;

    const float* xb = x + (size_t)b * (CIN * LIN);

    auto issue_chunk = [&](int c, int s) {
        // W: 320 rows x 8 u32 (two cp16 each)
#pragma unroll
        for (int i = 0; i < 3; i++) {
            int v = tid + i * 256;
            if (v < 640) {
                int row = v >> 1, half = v & 1;
                int tap = row >> 6, col = row & 63;
                uint32_t d = sbase + (uint32_t)(s * CV5_WS_ST + row * 12 + half * 4) * 4;
                cp16(d, g_wtb + (size_t)(tap * 128 + co0 + col) * 64 + c * 8 + half * 4);
            }
        }
        // X: 16 fp32 ci-rows x 260 floats (65 cp16 each), tail zero-filled
#pragma unroll
        for (int i = 0; i < 5; i++) {
            int v = tid + i * 256;
            if (v < 1040) {
                int row = v / 65, q = v - row * 65;
                int gl = lb + q * 4;
                int nb = (LIN - gl) * 4;
                nb = nb < 0 ? 0 : (nb > 16 ? 16 : nb);
                const float* sp = (nb > 0) ? (xb + (size_t)(c * 16 + row) * LIN + gl) : xb;
                uint32_t d = sbase + (uint32_t)(CV5_XS_BASE + s * CV5_XS_ST + row * 268 + q * 4) * 4;
                cp16n(d, sp, nb);
            }
        }
    };

    issue_chunk(0, 0);
    asm volatile("cp.async.commit_group;");
    issue_chunk(1, 1);
    asm volatile("cp.async.commit_group;");

    for (int c = 0; c < 8; c++) {
        const int s = c % 3;
        if (c < 7) {
            asm volatile("cp.async.wait_group 1;");
        } else {
            asm volatile("cp.async.wait_group 0;");
        }
        __syncthreads();

        const uint32_t* Wst = Su + s * CV5_WS_ST;
        const float* Xf = reinterpret_cast<const float*>(Su + CV5_XS_BASE + s * CV5_XS_ST);
        const float* Xr0 = Xf + (2 * t4)     * 268;
        const float* Xr1 = Xf + (2 * t4 + 1) * 268;
        const float* Xr2 = Xf + (2 * t4 + 8) * 268;
        const float* Xr3 = Xf + (2 * t4 + 9) * 268;
#pragma unroll
        for (int tap = 0; tap < 5; tap++) {
            uint32_t a[2][4];
#pragma unroll
            for (int mi = 0; mi < 2; mi++) {
                int row = tap * 64 + warp_m * 32 + mi * 16;
                a[mi][0] = Wst[(row + g)     * 12 + t4];
                a[mi][1] = Wst[(row + 8 + g) * 12 + t4];
                a[mi][2] = Wst[(row + g)     * 12 + t4 + 4];
                a[mi][3] = Wst[(row + 8 + g) * 12 + t4 + 4];
            }
#pragma unroll
            for (int ni = 0; ni < 8; ni++) {
                int col = warp_n * 64 + ni * 8 + g + tap;
                uint32_t b0 = pack_bf16(Xr0[col], Xr1[col]);
                uint32_t b1 = pack_bf16(Xr2[col], Xr3[col]);
                mma_bf16(acc[0][ni], a[0], b0, b1);
                mma_bf16(acc[1][ni], a[1], b0, b1);
            }
        }
        if (c + 2 < 8) {
            issue_chunk(c + 2, (c + 2) % 3);
            asm volatile("cp.async.commit_group;");
        }
    }

    uint32_t* ob = g_convb + (size_t)b * (64 * LOUT);
#pragma unroll
    for (int mi = 0; mi < 2; mi++) {
        int row0 = co0 + warp_m * 32 + mi * 16 + g;
        float bv0 = bias[row0];
        float bv1 = bias[row0 + 8];
#pragma unroll
        for (int ni = 0; ni < 8; ni++) {
            int l = lb + warp_n * 64 + ni * 8 + 2 * t4;
            if (l < LOUT) {
                ob[(size_t)row0 * 510 + (l >> 1)] =
                    pack_bf16(acc[mi][ni][0] + bv0, acc[mi][ni][1] + bv0);
                ob[(size_t)(row0 + 8) * 510 + (l >> 1)] =
                    pack_bf16(acc[mi][ni][2] + bv1, acc[mi][ni][3] + bv1);
            }
        }
    }
}

// =====================================================================
// xg1 via bf16 MMA (unchanged from R15)
// =====================================================================
#define XGC_STRIDE 68
#define XGC_SMEM_BYTES (2 * 128 * XGC_STRIDE * 4)   // 69632

__global__ __launch_bounds__(256, 2) void xg1e_kernel(
    const float* __restrict__ b1, const float* __restrict__ b2,
    float* __restrict__ C)
{
    extern __shared__ uint32_t smu[];
    uint32_t* As = smu;
    uint32_t* Bs = smu + 128 * XGC_STRIDE;
    const uint32_t sbase = smem_u32(smu);

    const int row0 = blockIdx.x * 128;
    const int tid  = threadIdx.x;
    const int warp = tid >> 5;
    const int lane = tid & 31;
    const int g    = lane >> 2;
    const int t4   = lane & 3;
    const int warp_m = warp >> 1;
    const int warp_n = warp & 1;

    for (int v = tid; v < 128 * 16; v += 256) {
        int r = v >> 4;
        int q = (v & 15) * 4;
        cp16(sbase + (uint32_t)(r * XGC_STRIDE + q) * 4,
             g_convb + (size_t)(row0 + r) * 64 + q);
    }
    for (int v = tid; v < 128 * 16; v += 256) {
        int r = v >> 4;
        int q = (v & 15) * 4;
        cp16(sbase + (uint32_t)((128 + r) * XGC_STRIDE + q) * 4,
             g_w1b + (size_t)r * 64 + q);
    }
    asm volatile("cp.async.commit_group;");
    asm volatile("cp.async.wait_group 0;");
    __syncthreads();

    float acc[2][8][4];
#pragma unroll
    for (int mi = 0; mi < 2; mi++)
#pragma unroll
        for (int ni = 0; ni < 8; ni++)
#pragma unroll
            for (int e = 0; e < 4; e++) acc[mi][ni][e] = 0.f;

#pragma unroll
    for (int k0 = 0; k0 < 64; k0 += 8) {
        uint32_t a[2][4];
#pragma unroll
        for (int mi = 0; mi < 2; mi++) {
            int row = warp_m * 32 + mi * 16;
            a[mi][0] = As[(row + g)     * XGC_STRIDE + k0 + t4];
            a[mi][1] = As[(row + 8 + g) * XGC_STRIDE + k0 + t4];
            a[mi][2] = As[(row + g)     * XGC_STRIDE + k0 + t4 + 4];
            a[mi][3] = As[(row + 8 + g) * XGC_STRIDE + k0 + t4 + 4];
        }
#pragma unroll
        for (int ni = 0; ni < 8; ni++) {
            int n = warp_n * 64 + ni * 8 + g;
            uint32_t b0 = Bs[n * XGC_STRIDE + k0 + t4];
            uint32_t b1 = Bs[n * XGC_STRIDE + k0 + t4 + 4];
            mma_bf16(acc[0][ni], a[0], b0, b1);
            mma_bf16(acc[1][ni], a[1], b0, b1);
        }
    }

#pragma unroll
    for (int mi = 0; mi < 2; mi++) {
        int r0 = row0 + warp_m * 32 + mi * 16 + g;
#pragma unroll
        for (int ni = 0; ni < 8; ni++) {
            int n = warp_n * 64 + ni * 8 + 2 * t4;
            float bb0 = b1[n] + b2[n];
            float bb1 = b1[n + 1] + b2[n + 1];
            *reinterpret_cast<float2*>(C + (size_t)r0 * 128 + n) =
                make_float2(acc[mi][ni][0] + bb0, acc[mi][ni][1] + bb1);
            *reinterpret_cast<float2*>(C + (size_t)(r0 + 8) * 128 + n) =
                make_float2(acc[mi][ni][2] + bb0, acc[mi][ni][3] + bb1);
        }
    }
}

// =====================================================================
// Fused LSTM1+2+3 (unchanged from R15)
// =====================================================================
__global__ __launch_bounds__(128, 4) void fused_lstm_kernel(
    const float* __restrict__ xg1,
    const float* __restrict__ Whh1,
    const float* __restrict__ Wih2, const float* __restrict__ Whh2,
    const float* __restrict__ bih2, const float* __restrict__ bhh2,
    const float* __restrict__ Wih3, const float* __restrict__ Whh3,
    const float* __restrict__ bih3, const float* __restrict__ bhh3,
    float* __restrict__ out)
{
    __shared__ __align__(16) float2 sw1go[32][32];
    __shared__ __align__(16) float2 sw3go[32][32];
    __shared__ __align__(16) float2 sw2h [16][32];
    __shared__ __align__(16) float2 h1r[2][2][32];
    __shared__ __align__(16) float2 h2r[2][2][16];
    __shared__ __align__(16) float2 h3r[2][2][32];
    __shared__ __align__(16) float  pre3r[2][2][128];

    const int tid  = threadIdx.x;
    const int wid  = tid >> 5;
    const int lane = tid & 31;
    const int b    = blockIdx.x;
    const int role = (wid + b) & 3;

    for (int v = tid; v < 1024; v += 128) {
        int k = v >> 5, j = v & 31;
        sw1go[k][j] = make_float2(Whh1[(size_t)(64 + j) * 32 + k], Whh1[(size_t)(96 + j) * 32 + k]);
        sw3go[k][j] = make_float2(Whh3[(size_t)(64 + j) * 32 + k], Whh3[(size_t)(96 + j) * 32 + k]);
    }
    for (int v = tid; v < 512; v += 128) {
        int k = v >> 5, j = v & 31;
        sw2h[k][j] = make_float2(Whh2[(size_t)j * 16 + k], Whh2[(size_t)(32 + j) * 16 + k]);
    }
    for (int v = tid; v < 128; v += 128) h1r[(v >> 6) & 1][(v >> 5) & 1][v & 31] = make_float2(0.f, 0.f);
    if (tid < 64)  h2r[(tid >> 5) & 1][(tid >> 4) & 1][tid & 15] = make_float2(0.f, 0.f);
    for (int v = tid; v < 128; v += 128) h3r[(v >> 6) & 1][(v >> 5) & 1][v & 31] = make_float2(0.f, 0.f);
    for (int v = tid; v < 512; v += 128) pre3r[(v >> 8) & 1][(v >> 7) & 1][v & 127] = 0.f;
    __syncthreads();

    if (role == 0) {
        float2 wif[32];
#pragma unroll
        for (int k = 0; k < 32; k++)
            wif[k] = make_float2(Whh1[(size_t)lane * 32 + k], Whh1[(size_t)(32 + lane) * 32 + k]);
        const float2* swgo = &sw1go[0][lane];
        const float* xb = xg1 + (size_t)b * TSEQ * 128 + lane;
        float pA0 = xb[0],   pA1 = xb[32],  pA2 = xb[64],  pA3 = xb[96];
        float pB0 = xb[128], pB1 = xb[160], pB2 = xb[192], pB3 = xb[224];
        float cst = 0.f;
        for (int m = 0; m < NWALL; m++) {
            if (m <= 509) {
                const int rs = (m - 1) & 1, ws = m & 1;
                float2 aifA = make_float2(pA0, pA1), agoA = make_float2(pA2, pA3);
                float2 aifB = make_float2(pB0, pB1), agoB = make_float2(pB2, pB3);
                if (m < 509) {
                    const float* xn = xb + (size_t)(2 * m + 2) * 128;
                    pA0 = __ldg(xn);       pA1 = __ldg(xn + 32);
                    pA2 = __ldg(xn + 64);  pA3 = __ldg(xn + 96);
                    pB0 = __ldg(xn + 128); pB1 = __ldg(xn + 160);
                    pB2 = __ldg(xn + 192); pB3 = __ldg(xn + 224);
                }
                float h = lstm32_step_sm(h1r[rs][1], wif, swgo, aifA, agoA, cst);
                h1r[ws][0][lane] = make_float2(h, h);
                __syncwarp();
                h = lstm32_step_sm(h1r[ws][0], wif, swgo, aifB, agoB, cst);
                h1r[ws][1][lane] = make_float2(h, h);
            }
            CTA_BAR();
        }
    } else if (role == 1) {
        const int pa = lane;
        const int pb = 32 + lane;
        float2 wi[32];
#pragma unroll
        for (int k = 0; k < 32; k++)
            wi[k] = make_float2(Wih2[(size_t)pa * 32 + k], Wih2[(size_t)pb * 32 + k]);
        const float2* swh = &sw2h[0][lane];
        const float2 bias2 = make_float2(bih2[pa] + bhh2[pa], bih2[pb] + bhh2[pb]);
        float cst = 0.f;
        for (int m = 0; m < NWALL; m++) {
            if (m >= 1 && m <= 510) {
                const int rs = (m - 1) & 1, ws = m & 1;
#pragma unroll
                for (int st = 0; st < 2; st++) {
                    float2 acc = bias2, accB = make_float2(0.f, 0.f);
                    const float2* h1p = h1r[rs][st];
#pragma unroll
                    for (int k = 0; k < 16; k++)
                        acc = ffma2(h1p[k], wi[k], acc);
#pragma unroll
                    for (int k = 16; k < 32; k++)
                        accB = ffma2(h1p[k], wi[k], accB);
                    const float2* h2p = (st == 0) ? h2r[rs][1] : h2r[ws][0];
#pragma unroll
                    for (int k = 0; k < 16; k++)
                        accB = ffma2(h2p[k], swh[k * 32], accB);
                    float va = acc.x + accB.x;
                    float vb = acc.y + accB.y;
                    float fpre = __shfl_sync(0xffffffffu, va, (lane & 15) + 16);
                    float opre = __shfl_sync(0xffffffffu, vb, (lane & 15) + 16);
                    if (lane < 16) {
                        float ig = sigmoid_fast(va);
                        float gg = tanh_fast(vb);
                        float fg = sigmoid_fast(fpre);
                        float og = sigmoid_fast(opre);
                        cst = fg * cst + ig * gg;
                        float h = og * tanh_fast(cst);
                        h2r[ws][st][lane] = make_float2(h, h);
                    }
                    __syncwarp();
                }
            }
            CTA_BAR();
        }
    } else if (role == 2) {
        float2 wa[16], wb[16];
#pragma unroll
        for (int k = 0; k < 16; k++) {
            wa[k] = make_float2(Wih3[(size_t)lane * 16 + k],        Wih3[(size_t)(32 + lane) * 16 + k]);
            wb[k] = make_float2(Wih3[(size_t)(64 + lane) * 16 + k], Wih3[(size_t)(96 + lane) * 16 + k]);
        }
        const float2 b3a = make_float2(bih3[lane] + bhh3[lane],           bih3[32 + lane] + bhh3[32 + lane]);
        const float2 b3b = make_float2(bih3[64 + lane] + bhh3[64 + lane], bih3[96 + lane] + bhh3[96 + lane]);
        for (int m = 0; m < NWALL; m++) {
            if (m >= 2 && m <= 511) {
                const int rs = (m - 1) & 1, ws = m & 1;
                float2 aa0 = b3a, ab0 = b3b, aa1 = b3a, ab1 = b3b;
                const float2* h2p0 = h2r[rs][0];
                const float2* h2p1 = h2r[rs][1];
#pragma unroll
                for (int k = 0; k < 16; k++) {
                    float2 hv0 = h2p0[k], hv1 = h2p1[k];
                    aa0 = ffma2(hv0, wa[k], aa0);
                    ab0 = ffma2(hv0, wb[k], ab0);
                    aa1 = ffma2(hv1, wa[k], aa1);
                    ab1 = ffma2(hv1, wb[k], ab1);
                }
                float* p0 = &pre3r[ws][0][lane];
                p0[0] = aa0.x; p0[32] = aa0.y; p0[64] = ab0.x; p0[96] = ab0.y;
                float* p1 = &pre3r[ws][1][lane];
                p1[0] = aa1.x; p1[32] = aa1.y; p1[64] = ab1.x; p1[96] = ab1.y;
            }
            CTA_BAR();
        }
    } else {
        float2 wif[32];
#pragma unroll
        for (int k = 0; k < 32; k++)
            wif[k] = make_float2(Whh3[(size_t)lane * 32 + k], Whh3[(size_t)(32 + lane) * 32 + k]);
        const float2* swgo = &sw3go[0][lane];
        float cst = 0.f, h3loc = 0.f;
        for (int m = 0; m < NWALL; m++) {
            if (m >= 3) {
                const int rs = (m - 1) & 1, ws = m & 1;
                const float* prA = &pre3r[rs][0][lane];
                float2 aif = make_float2(prA[0],  prA[32]);
                float2 ago = make_float2(prA[64], prA[96]);
                float h = lstm32_step_sm(h3r[rs][1], wif, swgo, aif, ago, cst);
                h3r[ws][0][lane] = make_float2(h, h);
                __syncwarp();
                const float* prB = &pre3r[rs][1][lane];
                aif = make_float2(prB[0],  prB[32]);
                ago = make_float2(prB[64], prB[96]);
                h3loc = lstm32_step_sm(h3r[ws][0], wif, swgo, aif, ago, cst);
                h3r[ws][1][lane] = make_float2(h3loc, h3loc);
            }
            CTA_BAR();
        }
        out[(size_t)b * 32 + lane] = h3loc;
    }
}

// ---------------- launch ----------------
extern "C" void kernel_launch(void* const* d_in, const int* in_sizes, int n_in,
                              void* d_out, int out_size)
{
    const float* x      = (const float*)d_in[0];
    const float* conv_w = (const float*)d_in[1];
    const float* conv_b = (const float*)d_in[2];
    const float* Wih1   = (const float*)d_in[3];
    const float* Whh1   = (const float*)d_in[4];
    const float* bih1   = (const float*)d_in[5];
    const float* bhh1   = (const float*)d_in[6];
    const float* Wih2   = (const float*)d_in[7];
    const float* Whh2   = (const float*)d_in[8];
    const float* bih2   = (const float*)d_in[9];
    const float* bhh2   = (const float*)d_in[10];
    const float* Wih3   = (const float*)d_in[11];
    const float* Whh3   = (const float*)d_in[12];
    const float* bih3   = (const float*)d_in[13];
    const float* bhh3   = (const float*)d_in[14];
    float* out = (float*)d_out;

    float* xg1_p;
    cudaGetSymbolAddress((void**)&xg1_p, g_xg1);

    cudaFuncSetAttribute(conv5_kernel, cudaFuncAttributeMaxDynamicSharedMemorySize, CV5_SMEM_BYTES);
    cudaFuncSetAttribute(xg1e_kernel,  cudaFuncAttributeMaxDynamicSharedMemorySize, XGC_SMEM_BYTES);

    // 0) prepack (weights only)
    prep_wb_kernel<<<160, 256>>>(conv_w);
    prep_w1_kernel<<<32, 256>>>(Wih1);

    // 1) conv (fp32 X direct, inline bf16 pack)
    conv5_kernel<<<dim3(4, BATCH, 2), 256, CV5_SMEM_BYTES>>>(x, conv_b);

    // 2) xg1
    xg1e_kernel<<<MROWS / 128, 256, XGC_SMEM_BYTES>>>(bih1, bhh1, xg1_p);

    // 3) fused LSTM1+2+3 -> d_out
    fused_lstm_kernel<<<BATCH, 128>>>(xg1_p, Whh1, Wih2, Whh2, bih2, bhh2,
                                      Wih3, Whh3, bih3, bhh3, out);

    (void)in_sizes; (void)n_in; (void)out_size;
}

// round 17
// speedup vs baseline: 1.0057x; 1.0057x over previous
#include <cuda_runtime.h>
#include <cuda_bf16.h>
#include <cstdint>

// Problem constants
#define BATCH   512
#define CIN     128
#define LIN     1024
#define KW      5
#define LOUT    1020
#define TSEQ    1020
#define H1      32
#define H2      16
#define H3      32
#define MROWS   (BATCH * TSEQ)   // 522240
#define NWALL   (TSEQ / 2 + 3)   // 513

// ---------------- scratch ----------------
__device__ uint32_t g_convb[(size_t)BATCH * 64 * LOUT];    // bf16-pair conv out
__device__ uint32_t g_xg1b [(size_t)MROWS * 64];           // bf16-pair xg1
__device__ uint32_t g_wtb  [5 * 128 * 64];                 // bf16-pair conv W
__device__ uint32_t g_w1b  [128 * 64];                     // bf16-pair Wih1
__device__ uint32_t g_xp   [(size_t)BATCH * 64 * LIN];     // bf16-pair X

// ---------------- helpers ----------------
__device__ __forceinline__ float tanh_fast(float x) {
    float r; asm("tanh.approx.f32 %0, %1;" : "=f"(r) : "f"(x));
    return r;
}
__device__ __forceinline__ float sigmoid_fast(float x) {
    float r; asm("tanh.approx.f32 %0, %1;" : "=f"(r) : "f"(x * 0.5f));
    return fmaf(r, 0.5f, 0.5f);
}
__device__ __forceinline__ uint32_t pack_bf16(float lo, float hi) {
    uint32_t r;
    asm("cvt.rn.bf16x2.f32 %0, %1, %2;" : "=r"(r) : "f"(hi), "f"(lo));
    return r;
}
__device__ __forceinline__ float bf_sel(uint32_t u, bool odd) {
    return __uint_as_float(odd ? (u & 0xffff0000u) : (u << 16));
}
__device__ __forceinline__ void mma_bf16(float c[4], const uint32_t a[4], uint32_t b0, uint32_t b1) {
    asm volatile(
        "mma.sync.aligned.m16n8k16.row.col.f32.bf16.bf16.f32 "
        "{%0,%1,%2,%3}, {%4,%5,%6,%7}, {%8,%9}, {%0,%1,%2,%3};"
        : "+f"(c[0]), "+f"(c[1]), "+f"(c[2]), "+f"(c[3])
        : "r"(a[0]), "r"(a[1]), "r"(a[2]), "r"(a[3]), "r"(b0), "r"(b1));
}
__device__ __forceinline__ float2 ffma2(float2 a, float2 b, float2 c) {
    unsigned long long ua, ub, uc, ur;
    ua = *reinterpret_cast<unsigned long long*>(&a);
    ub = *reinterpret_cast<unsigned long long*>(&b);
    uc = *reinterpret_cast<unsigned long long*>(&c);
    asm("fma.rn.f32x2 %0, %1, %2, %3;" : "=l"(ur) : "l"(ua), "l"(ub), "l"(uc));
    return *reinterpret_cast<float2*>(&ur);
}
__device__ __forceinline__ uint32_t smem_u32(const void* p) {
    uint32_t a;
    asm("{ .reg .u64 t; cvta.to.shared.u64 t, %1; cvt.u32.u64 %0, t; }" : "=r"(a) : "l"(p));
    return a;
}
__device__ __forceinline__ void cp16(uint32_t dst, const void* src) {
    asm volatile("cp.async.ca.shared.global [%0], [%1], 16;" :: "r"(dst), "l"(src));
}
__device__ __forceinline__ void cp16n(uint32_t dst, const void* src, int nbytes) {
    asm volatile("cp.async.ca.shared.global [%0], [%1], 16, %2;" :: "r"(dst), "l"(src), "r"(nbytes));
}
#define CTA_BAR() asm volatile("bar.sync 0;" ::: "memory")

// H=32 LSTM cell step; i/f weights in regs, g/o weights from smem
__device__ __forceinline__ float lstm32_step_sm(
    const float2* __restrict__ hp,
    const float2* __restrict__ wif,
    const float2* __restrict__ swgo,
    float2 aif, float2 ago, float& cst)
{
    float2 aifB = make_float2(0.f, 0.f), agoB = make_float2(0.f, 0.f);
#pragma unroll
    for (int k = 0; k < 16; k++) {
        float2 hv = hp[k];
        aif = ffma2(hv, wif[k], aif);
        ago = ffma2(hv, swgo[k * 32], ago);
    }
#pragma unroll
    for (int k = 16; k < 32; k++) {
        float2 hv = hp[k];
        aifB = ffma2(hv, wif[k], aifB);
        agoB = ffma2(hv, swgo[k * 32], agoB);
    }
    float ig = sigmoid_fast(aif.x + aifB.x);
    float fg = sigmoid_fast(aif.y + aifB.y);
    float gg = tanh_fast(ago.x + agoB.x);
    float og = sigmoid_fast(ago.y + agoB.y);
    cst = fg * cst + ig * gg;
    return og * tanh_fast(cst);
}

// =====================================================================
// Prepack kernels
// =====================================================================
__global__ void prep_wb_kernel(const float* __restrict__ w) {
    int i = blockIdx.x * 256 + threadIdx.x;
    if (i < 5 * 128 * 64) {
        int kp = i & 63;
        int r  = i >> 6;
        int co  = r & 127;
        int tap = r >> 7;
        float lo = w[((size_t)co * 128 + 2 * kp)     * 5 + tap];
        float hi = w[((size_t)co * 128 + 2 * kp + 1) * 5 + tap];
        g_wtb[i] = pack_bf16(lo, hi);
    }
}
__global__ void prep_w1_kernel(const float* __restrict__ W) {
    int i = blockIdx.x * 256 + threadIdx.x;
    if (i < 128 * 64) {
        int kp = i & 63;
        int r  = i >> 6;
        float2 wv = *reinterpret_cast<const float2*>(W + (size_t)r * 128 + 2 * kp);
        g_w1b[i] = pack_bf16(wv.x, wv.y);
    }
}
__global__ __launch_bounds__(256) void prep_xp_kernel(const float* __restrict__ x) {
    size_t idx = (size_t)blockIdx.x * 256 + threadIdx.x;
    if (idx < (size_t)BATCH * 64 * LIN) {
        int l  = (int)(idx & 1023);
        size_t r = idx >> 10;
        int cp = (int)(r & 63);
        size_t b = r >> 6;
        float lo = x[(b * 128 + 2 * cp)     * LIN + l];
        float hi = x[(b * 128 + 2 * cp + 1) * LIN + l];
        g_xp[idx] = pack_bf16(lo, hi);
    }
}

// =====================================================================
// conv1d via bf16 m16n8k16 MMA, 3-stage cp.async (R15 known-good)
// =====================================================================
#define CV4_WS_ST   (320 * 12)
#define CV4_XS_ST   (8 * 264)
#define CV4_XS_BASE (3 * CV4_WS_ST)
#define CV4_SMEM_BYTES ((3 * CV4_WS_ST + 3 * CV4_XS_ST) * 4)   // 71424

__global__ __launch_bounds__(256, 2) void conv4_kernel(
    const float* __restrict__ bias)
{
    extern __shared__ uint32_t smu[];
    const uint32_t sbase = smem_u32(smu);
    const uint32_t* Su = smu;

    const int b   = blockIdx.y;
    const int lb  = blockIdx.x * 256;
    const int co0 = blockIdx.z * 64;
    const int tid = threadIdx.x;
    const int warp = tid >> 5;
    const int lane = tid & 31;
    const int g   = lane >> 2;
    const int t4  = lane & 3;
    const int warp_m = warp >> 2;
    const int warp_n = warp & 3;

    float acc[2][8][4];
#pragma unroll
    for (int mi = 0; mi < 2; mi++)
#pragma unroll
        for (int ni = 0; ni < 8; ni++)
#pragma unroll
            for (int e = 0; e < 4; e++) acc[mi][ni][e] = 0.f;

    const uint32_t* xpb = g_xp + (size_t)b * 64 * LIN;

    auto issue_chunk = [&](int c, int s) {
#pragma unroll
        for (int i = 0; i < 3; i++) {
            int v = tid + i * 256;
            if (v < 640) {
                int row = v >> 1, half = v & 1;
                int tap = row >> 6, col = row & 63;
                uint32_t d = sbase + (uint32_t)(s * CV4_WS_ST + row * 12 + half * 4) * 4;
                cp16(d, g_wtb + (size_t)(tap * 128 + co0 + col) * 64 + c * 8 + half * 4);
            }
        }
#pragma unroll
        for (int i = 0; i < 3; i++) {
            int v = tid + i * 256;
            if (v < 520) {
                int row = v / 65, q = v - row * 65;
                int gl = lb + q * 4;
                int nb = (LIN - gl) * 4;
                nb = nb < 0 ? 0 : (nb > 16 ? 16 : nb);
                const uint32_t* sp = (nb > 0) ? (xpb + (size_t)(c * 8 + row) * LIN + gl) : xpb;
                uint32_t d = sbase + (uint32_t)(CV4_XS_BASE + s * CV4_XS_ST + row * 264 + q * 4) * 4;
                cp16n(d, sp, nb);
            }
        }
    };

    issue_chunk(0, 0);
    asm volatile("cp.async.commit_group;");
    issue_chunk(1, 1);
    asm volatile("cp.async.commit_group;");

    for (int c = 0; c < 8; c++) {
        const int s = c % 3;
        if (c < 7) {
            asm volatile("cp.async.wait_group 1;");
        } else {
            asm volatile("cp.async.wait_group 0;");
        }
        __syncthreads();

        const uint32_t* Wst = Su + s * CV4_WS_ST;
        const uint32_t* Xst = Su + CV4_XS_BASE + s * CV4_XS_ST;
#pragma unroll
        for (int tap = 0; tap < 5; tap++) {
            uint32_t a[2][4];
#pragma unroll
            for (int mi = 0; mi < 2; mi++) {
                int row = tap * 64 + warp_m * 32 + mi * 16;
                a[mi][0] = Wst[(row + g)     * 12 + t4];
                a[mi][1] = Wst[(row + 8 + g) * 12 + t4];
                a[mi][2] = Wst[(row + g)     * 12 + t4 + 4];
                a[mi][3] = Wst[(row + 8 + g) * 12 + t4 + 4];
            }
#pragma unroll
            for (int ni = 0; ni < 8; ni++) {
                int col = warp_n * 64 + ni * 8 + g + tap;
                uint32_t b0 = Xst[t4 * 264 + col];
                uint32_t b1 = Xst[(t4 + 4) * 264 + col];
                mma_bf16(acc[0][ni], a[0], b0, b1);
                mma_bf16(acc[1][ni], a[1], b0, b1);
            }
        }
        if (c + 2 < 8) {
            issue_chunk(c + 2, (c + 2) % 3);
            asm volatile("cp.async.commit_group;");
        }
    }

    uint32_t* ob = g_convb + (size_t)b * (64 * LOUT);
#pragma unroll
    for (int mi = 0; mi < 2; mi++) {
        int row0 = co0 + warp_m * 32 + mi * 16 + g;
        float bv0 = bias[row0];
        float bv1 = bias[row0 + 8];
#pragma unroll
        for (int ni = 0; ni < 8; ni++) {
            int l = lb + warp_n * 64 + ni * 8 + 2 * t4;
            if (l < LOUT) {
                ob[(size_t)row0 * 510 + (l >> 1)] =
                    pack_bf16(acc[mi][ni][0] + bv0, acc[mi][ni][1] + bv0);
                ob[(size_t)(row0 + 8) * 510 + (l >> 1)] =
                    pack_bf16(acc[mi][ni][2] + bv1, acc[mi][ni][3] + bv1);
            }
        }
    }
}

// =====================================================================
// xg1: bf16 MMA, cp.async prepacked A+W, PACKED bf16 output.
// =====================================================================
#define XGC_STRIDE 68
#define XGC_SMEM_BYTES (2 * 128 * XGC_STRIDE * 4)   // 69632

__global__ __launch_bounds__(256, 2) void xg1f_kernel(
    const float* __restrict__ b1, const float* __restrict__ b2)
{
    extern __shared__ uint32_t smu[];
    uint32_t* As = smu;
    uint32_t* Bs = smu + 128 * XGC_STRIDE;
    const uint32_t sbase = smem_u32(smu);

    const int row0 = blockIdx.x * 128;
    const int tid  = threadIdx.x;
    const int warp = tid >> 5;
    const int lane = tid & 31;
    const int g    = lane >> 2;
    const int t4   = lane & 3;
    const int warp_m = warp >> 1;
    const int warp_n = warp & 1;

    for (int v = tid; v < 128 * 16; v += 256) {
        int r = v >> 4;
        int q = (v & 15) * 4;
        cp16(sbase + (uint32_t)(r * XGC_STRIDE + q) * 4,
             g_convb + (size_t)(row0 + r) * 64 + q);
    }
    for (int v = tid; v < 128 * 16; v += 256) {
        int r = v >> 4;
        int q = (v & 15) * 4;
        cp16(sbase + (uint32_t)((128 + r) * XGC_STRIDE + q) * 4,
             g_w1b + (size_t)r * 64 + q);
    }
    asm volatile("cp.async.commit_group;");
    asm volatile("cp.async.wait_group 0;");
    __syncthreads();

    float acc[2][8][4];
#pragma unroll
    for (int mi = 0; mi < 2; mi++)
#pragma unroll
        for (int ni = 0; ni < 8; ni++)
#pragma unroll
            for (int e = 0; e < 4; e++) acc[mi][ni][e] = 0.f;

#pragma unroll
    for (int k0 = 0; k0 < 64; k0 += 8) {
        uint32_t a[2][4];
#pragma unroll
        for (int mi = 0; mi < 2; mi++) {
            int row = warp_m * 32 + mi * 16;
            a[mi][0] = As[(row + g)     * XGC_STRIDE + k0 + t4];
            a[mi][1] = As[(row + 8 + g) * XGC_STRIDE + k0 + t4];
            a[mi][2] = As[(row + g)     * XGC_STRIDE + k0 + t4 + 4];
            a[mi][3] = As[(row + 8 + g) * XGC_STRIDE + k0 + t4 + 4];
        }
#pragma unroll
        for (int ni = 0; ni < 8; ni++) {
            int n = warp_n * 64 + ni * 8 + g;
            uint32_t b0 = Bs[n * XGC_STRIDE + k0 + t4];
            uint32_t b1 = Bs[n * XGC_STRIDE + k0 + t4 + 4];
            mma_bf16(acc[0][ni], a[0], b0, b1);
            mma_bf16(acc[1][ni], a[1], b0, b1);
        }
    }

#pragma unroll
    for (int mi = 0; mi < 2; mi++) {
        int r0 = row0 + warp_m * 32 + mi * 16 + g;
#pragma unroll
        for (int ni = 0; ni < 8; ni++) {
            int n = warp_n * 64 + ni * 8 + 2 * t4;   // even
            float bb0 = b1[n] + b2[n];
            float bb1 = b1[n + 1] + b2[n + 1];
            g_xg1b[(size_t)r0 * 64 + (n >> 1)] =
                pack_bf16(acc[mi][ni][0] + bb0, acc[mi][ni][1] + bb1);
            g_xg1b[(size_t)(r0 + 8) * 64 + (n >> 1)] =
                pack_bf16(acc[mi][ni][2] + bb0, acc[mi][ni][3] + bb1);
        }
    }
}

// =====================================================================
// Fused LSTM1+2+3 (R15 structure; role0 reads packed bf16 xg1)
// =====================================================================
__global__ __launch_bounds__(128, 4) void fused_lstm_kernel(
    const uint32_t* __restrict__ xg1b,
    const float* __restrict__ Whh1,
    const float* __restrict__ Wih2, const float* __restrict__ Whh2,
    const float* __restrict__ bih2, const float* __restrict__ bhh2,
    const float* __restrict__ Wih3, const float* __restrict__ Whh3,
    const float* __restrict__ bih3, const float* __restrict__ bhh3,
    float* __restrict__ out)
{
    __shared__ __align__(16) float2 sw1go[32][32];
    __shared__ __align__(16) float2 sw3go[32][32];
    __shared__ __align__(16) float2 sw2h [16][32];
    __shared__ __align__(16) float2 h1r[2][2][32];
    __shared__ __align__(16) float2 h2r[2][2][16];
    __shared__ __align__(16) float2 h3r[2][2][32];
    __shared__ __align__(16) float  pre3r[2][2][128];

    const int tid  = threadIdx.x;
    const int wid  = tid >> 5;
    const int lane = tid & 31;
    const int b    = blockIdx.x;
    const int role = (wid + b) & 3;

    for (int v = tid; v < 1024; v += 128) {
        int k = v >> 5, j = v & 31;
        sw1go[k][j] = make_float2(Whh1[(size_t)(64 + j) * 32 + k], Whh1[(size_t)(96 + j) * 32 + k]);
        sw3go[k][j] = make_float2(Whh3[(size_t)(64 + j) * 32 + k], Whh3[(size_t)(96 + j) * 32 + k]);
    }
    for (int v = tid; v < 512; v += 128) {
        int k = v >> 5, j = v & 31;
        sw2h[k][j] = make_float2(Whh2[(size_t)j * 16 + k], Whh2[(size_t)(32 + j) * 16 + k]);
    }
    for (int v = tid; v < 128; v += 128) h1r[(v >> 6) & 1][(v >> 5) & 1][v & 31] = make_float2(0.f, 0.f);
    if (tid < 64)  h2r[(tid >> 5) & 1][(tid >> 4) & 1][tid & 15] = make_float2(0.f, 0.f);
    for (int v = tid; v < 128; v += 128) h3r[(v >> 6) & 1][(v >> 5) & 1][v & 31] = make_float2(0.f, 0.f);
    for (int v = tid; v < 512; v += 128) pre3r[(v >> 8) & 1][(v >> 7) & 1][v & 127] = 0.f;
    __syncthreads();

    if (role == 0) {
        float2 wif[32];
#pragma unroll
        for (int k = 0; k < 32; k++)
            wif[k] = make_float2(Whh1[(size_t)lane * 32 + k], Whh1[(size_t)(32 + lane) * 32 + k]);
        const float2* swgo = &sw1go[0][lane];
        const uint32_t* xb = xg1b + (size_t)b * TSEQ * 64 + (lane >> 1);
        const bool odd = lane & 1;
        uint32_t pA0 = xb[0],  pA1 = xb[16], pA2 = xb[32], pA3 = xb[48];
        uint32_t pB0 = xb[64], pB1 = xb[80], pB2 = xb[96], pB3 = xb[112];
        float cst = 0.f;
        for (int m = 0; m < NWALL; m++) {
            if (m <= 509) {
                const int rs = (m - 1) & 1, ws = m & 1;
                float2 aifA = make_float2(bf_sel(pA0, odd), bf_sel(pA1, odd));
                float2 agoA = make_float2(bf_sel(pA2, odd), bf_sel(pA3, odd));
                float2 aifB = make_float2(bf_sel(pB0, odd), bf_sel(pB1, odd));
                float2 agoB = make_float2(bf_sel(pB2, odd), bf_sel(pB3, odd));
                if (m < 509) {
                    const uint32_t* xn = xb + (size_t)(2 * m + 2) * 64;
                    pA0 = __ldg(xn);      pA1 = __ldg(xn + 16);
                    pA2 = __ldg(xn + 32); pA3 = __ldg(xn + 48);
                    pB0 = __ldg(xn + 64); pB1 = __ldg(xn + 80);
                    pB2 = __ldg(xn + 96); pB3 = __ldg(xn + 112);
                }
                float h = lstm32_step_sm(h1r[rs][1], wif, swgo, aifA, agoA, cst);
                h1r[ws][0][lane] = make_float2(h, h);
                __syncwarp();
                h = lstm32_step_sm(h1r[ws][0], wif, swgo, aifB, agoB, cst);
                h1r[ws][1][lane] = make_float2(h, h);
            }
            CTA_BAR();
        }
    } else if (role == 1) {
        const int pa = lane;
        const int pb = 32 + lane;
        float2 wi[32];
#pragma unroll
        for (int k = 0; k < 32; k++)
            wi[k] = make_float2(Wih2[(size_t)pa * 32 + k], Wih2[(size_t)pb * 32 + k]);
        const float2* swh = &sw2h[0][lane];
        const float2 bias2 = make_float2(bih2[pa] + bhh2[pa], bih2[pb] + bhh2[pb]);
        float cst = 0.f;
        for (int m = 0; m < NWALL; m++) {
            if (m >= 1 && m <= 510) {
                const int rs = (m - 1) & 1, ws = m & 1;
#pragma unroll
                for (int st = 0; st < 2; st++) {
                    float2 acc = bias2, accB = make_float2(0.f, 0.f);
                    const float2* h1p = h1r[rs][st];
#pragma unroll
                    for (int k = 0; k < 16; k++)
                        acc = ffma2(h1p[k], wi[k], acc);
#pragma unroll
                    for (int k = 16; k < 32; k++)
                        accB = ffma2(h1p[k], wi[k], accB);
                    const float2* h2p = (st == 0) ? h2r[rs][1] : h2r[ws][0];
#pragma unroll
                    for (int k = 0; k < 16; k++)
                        accB = ffma2(h2p[k], swh[k * 32], accB);
                    float va = acc.x + accB.x;
                    float vb = acc.y + accB.y;
                    float fpre = __shfl_sync(0xffffffffu, va, (lane & 15) + 16);
                    float opre = __shfl_sync(0xffffffffu, vb, (lane & 15) + 16);
                    if (lane < 16) {
                        float ig = sigmoid_fast(va);
                        float gg = tanh_fast(vb);
                        float fg = sigmoid_fast(fpre);
                        float og = sigmoid_fast(opre);
                        cst = fg * cst + ig * gg;
                        float h = og * tanh_fast(cst);
                        h2r[ws][st][lane] = make_float2(h, h);
                    }
                    __syncwarp();
                }
            }
            CTA_BAR();
        }
    } else if (role == 2) {
        float2 wa[16], wb[16];
#pragma unroll
        for (int k = 0; k < 16; k++) {
            wa[k] = make_float2(Wih3[(size_t)lane * 16 + k],        Wih3[(size_t)(32 + lane) * 16 + k]);
            wb[k] = make_float2(Wih3[(size_t)(64 + lane) * 16 + k], Wih3[(size_t)(96 + lane) * 16 + k]);
        }
        const float2 b3a = make_float2(bih3[lane] + bhh3[lane],           bih3[32 + lane] + bhh3[32 + lane]);
        const float2 b3b = make_float2(bih3[64 + lane] + bhh3[64 + lane], bih3[96 + lane] + bhh3[96 + lane]);
        for (int m = 0; m < NWALL; m++) {
            if (m >= 2 && m <= 511) {
                const int rs = (m - 1) & 1, ws = m & 1;
                float2 aa0 = b3a, ab0 = b3b, aa1 = b3a, ab1 = b3b;
                const float2* h2p0 = h2r[rs][0];
                const float2* h2p1 = h2r[rs][1];
#pragma unroll
                for (int k = 0; k < 16; k++) {
                    float2 hv0 = h2p0[k], hv1 = h2p1[k];
                    aa0 = ffma2(hv0, wa[k], aa0);
                    ab0 = ffma2(hv0, wb[k], ab0);
                    aa1 = ffma2(hv1, wa[k], aa1);
                    ab1 = ffma2(hv1, wb[k], ab1);
                }
                float* p0 = &pre3r[ws][0][lane];
                p0[0] = aa0.x; p0[32] = aa0.y; p0[64] = ab0.x; p0[96] = ab0.y;
                float* p1 = &pre3r[ws][1][lane];
                p1[0] = aa1.x; p1[32] = aa1.y; p1[64] = ab1.x; p1[96] = ab1.y;
            }
            CTA_BAR();
        }
    } else {
        float2 wif[32];
#pragma unroll
        for (int k = 0; k < 32; k++)
            wif[k] = make_float2(Whh3[(size_t)lane * 32 + k], Whh3[(size_t)(32 + lane) * 32 + k]);
        const float2* swgo = &sw3go[0][lane];
        float cst = 0.f, h3loc = 0.f;
        for (int m = 0; m < NWALL; m++) {
            if (m >= 3) {
                const int rs = (m - 1) & 1, ws = m & 1;
                const float* prA = &pre3r[rs][0][lane];
                float2 aif = make_float2(prA[0],  prA[32]);
                float2 ago = make_float2(prA[64], prA[96]);
                float h = lstm32_step_sm(h3r[rs][1], wif, swgo, aif, ago, cst);
                h3r[ws][0][lane] = make_float2(h, h);
                __syncwarp();
                const float* prB = &pre3r[rs][1][lane];
                aif = make_float2(prB[0],  prB[32]);
                ago = make_float2(prB[64], prB[96]);
                h3loc = lstm32_step_sm(h3r[ws][0], wif, swgo, aif, ago, cst);
                h3r[ws][1][lane] = make_float2(h3loc, h3loc);
            }
            CTA_BAR();
        }
        out[(size_t)b * 32 + lane] = h3loc;
    }
}

// ---------------- launch ----------------
extern "C" void kernel_launch(void* const* d_in, const int* in_sizes, int n_in,
                              void* d_out, int out_size)
{
    const float* x      = (const float*)d_in[0];
    const float* conv_w = (const float*)d_in[1];
    const float* conv_b = (const float*)d_in[2];
    const float* Wih1   = (const float*)d_in[3];
    const float* Whh1   = (const float*)d_in[4];
    const float* bih1   = (const float*)d_in[5];
    const float* bhh1   = (const float*)d_in[6];
    const float* Wih2   = (const float*)d_in[7];
    const float* Whh2   = (const float*)d_in[8];
    const float* bih2   = (const float*)d_in[9];
    const float* bhh2   = (const float*)d_in[10];
    const float* Wih3   = (const float*)d_in[11];
    const float* Whh3   = (const float*)d_in[12];
    const float* bih3   = (const float*)d_in[13];
    const float* bhh3   = (const float*)d_in[14];
    float* out = (float*)d_out;

    uint32_t* xg1b_p;
    cudaGetSymbolAddress((void**)&xg1b_p, g_xg1b);

    cudaFuncSetAttribute(conv4_kernel, cudaFuncAttributeMaxDynamicSharedMemorySize, CV4_SMEM_BYTES);
    cudaFuncSetAttribute(xg1f_kernel,  cudaFuncAttributeMaxDynamicSharedMemorySize, XGC_SMEM_BYTES);

    // 0) prepack
    prep_wb_kernel<<<160, 256>>>(conv_w);
    prep_w1_kernel<<<32, 256>>>(Wih1);
    prep_xp_kernel<<<(int)(((size_t)BATCH * 64 * LIN + 255) / 256), 256>>>(x);

    // 1) conv (R15 known-good)
    conv4_kernel<<<dim3(4, BATCH, 2), 256, CV4_SMEM_BYTES>>>(conv_b);

    // 2) xg1 (bf16 in + out)
    xg1f_kernel<<<MROWS / 128, 256, XGC_SMEM_BYTES>>>(bih1, bhh1);

    // 3) fused LSTM1+2+3 (role0 reads packed bf16)
    fused_lstm_kernel<<<BATCH, 128>>>(xg1b_p, Whh1, Wih2, Whh2, bih2, bhh2,
                                      Wih3, Whh3, bih3, bhh3, out);

    (void)in_sizes; (void)n_in; (void)out_size;
}